// round 13
// baseline (speedup 1.0000x reference)
#include <cuda_runtime.h>

// Problem: volume [40,40,40,32] f32, M [32,32], P [32,32] -> Nk [59319,32]
//   b = (k1*39 + k2)*39 + k3
//   Nk[b,i] = sum_j x[b,j] * P[i,j] * cos(k1*a_ij) * cos(k2*a_ij) * cos(k3*a_ij)
//   a_ij = 2pi/(i*32+j+2),  x = (2x2x2 mean pool) @ M^T
//
// R13: phase E = R9's register-resident Chebyshev march (1 warp = 1 pair,
// all j in 16 f32x2 regs), but: TPB=96 (3 pairs/block, no idle warps),
// 4 blocks/SM (regs capped 170), single wave (507 <= 592), and pooling
// restructured as dd-summed row staging + sliding-window combine (2x fewer
// LDGs, no dependent load chains).
#define NP    39
#define NPAIR (39*39)     // 1521 = 507 * 3
#define PPB   3
#define TPB   96          // 3 warps; warp w <-> pair lp = w
#define PI2F  6.2831853071795864769f

typedef unsigned long long ull;

__device__ float g_tab[39 * 1024];   // tab[k][j*32+i] = cos(k*2pi/(i*32+j+2))

// ---- f32x2 packed math (sm_103a) ------------------------------------------
__device__ __forceinline__ ull f2_fma(ull a, ull b, ull c) {
    ull d; asm("fma.rn.f32x2 %0, %1, %2, %3;" : "=l"(d) : "l"(a), "l"(b), "l"(c)); return d;
}
__device__ __forceinline__ ull f2_add(ull a, ull b) {
    ull d; asm("add.rn.f32x2 %0, %1, %2;" : "=l"(d) : "l"(a), "l"(b)); return d;
}
__device__ __forceinline__ ull f2_pack2(float lo, float hi) {
    ull d; asm("mov.b64 %0, {%1, %2};" : "=l"(d) : "f"(lo), "f"(hi)); return d;
}
__device__ __forceinline__ float2 f2_unpack(ull v) {
    float2 r; asm("mov.b64 {%0, %1}, %2;" : "=f"(r.x), "=f"(r.y) : "l"(v)); return r;
}

// ---------------------------------------------------------------------------
// Kernel 0: cos table via Chebyshev recurrence. grid 4 x 256.
// ---------------------------------------------------------------------------
__global__ void k_pre() {
    int t = blockIdx.x * 256 + threadIdx.x;   // t = j*32 + i
    int i = t & 31, j = t >> 5;
    float a  = PI2F / (float)(i * 32 + j + 2);
    float c1 = cosf(a);
    float twoc = 2.0f * c1;
    float cm2 = 1.0f, cm1 = c1;
    g_tab[t]        = 1.0f;
    g_tab[1024 + t] = c1;
#pragma unroll
    for (int k = 2; k < 39; k++) {
        float ck = twoc * cm1 - cm2;
        g_tab[k * 1024 + t] = ck;
        cm2 = cm1; cm1 = ck;
    }
}

// ---------------------------------------------------------------------------
// Main kernel: grid 507 x 96 threads, 48.2 KB STATIC smem, 4 blocks/SM.
// ---------------------------------------------------------------------------
// smem float offsets (16B-aligned where vector-accessed):
#define S_PT    0        // 1056   P^T padded [j*33 + i]  (seeds read this)
#define S_MT    1056     // 1024   MT[l*32 + j] = M[j][l]
#define S_SDH   2080     // 4*40*36 = 5760  sdh2[hh][k3r*36 + ch]  (dd-summed)
#define S_X     2080     // 3*1248 = 3744   x'[lp][k3*32+j]  (overlaps SDH)
#define S_POOL  7840     // 3*1404 = 4212   pooled[lp][k3*36 + ch]
#define SM_FLOATS 12052  // 48208 bytes

__global__ void __launch_bounds__(TPB, 4) k_main(
    const float* __restrict__ vol, const float* __restrict__ Mw,
    const float* __restrict__ P, float* __restrict__ out)
{
    __shared__ float sm[SM_FLOATS];
    const int tid  = threadIdx.x;
    const int lane = tid & 31;
    const int wid  = tid >> 5;                 // = pair within block (0..2)
    const int pairb = blockIdx.x * PPB;        // k2b = pairb%39, 3-aligned
    const int k1b  = pairb / 39;
    const int k2b  = pairb - k1b * 39;

    // -------- Phase A: stage P^T (padded), MT; dd-summed volume rows --------
    for (int g = tid; g < 1024; g += TPB) {
        sm[S_PT + (g & 31) * 33 + (g >> 5)] = P[g];           // PT[j][i] = P[i][j]
        sm[S_MT + g] = Mw[(g & 31) * 32 + (g >> 5)];          // MT[l][j] = M[j][l]
    }
    // sdh2[hh][k3r][ch] = vol[k1b][k2b+hh][k3r][ch] + vol[k1b+1][k2b+hh][k3r][ch]
    // 4 hh-rows shared by the block's 3 pairs. 1280 jobs, 2 independent LDGs each.
    for (int idx = tid; idx < 1280; idx += TPB) {
        int hh  = idx / 320;
        int r   = idx - hh * 320;
        int k3r = r >> 3;
        int cq  = r & 7;
        const float* base = vol + ((k1b * 40 + k2b + hh) * 40 + k3r) * 32 + cq * 4;
        float4 v0 = *(const float4*)(base);
        float4 v1 = *(const float4*)(base + 51200);           // dd = 1
        float4 s  = make_float4(v0.x + v1.x, v0.y + v1.y, v0.z + v1.z, v0.w + v1.w);
        *(float4*)&sm[S_SDH + hh * 1440 + k3r * 36 + cq * 4] = s;
    }
    __syncthreads();

    // -------- Phase B2: sliding-window combine -> pooled (x 0.125) --------
    for (int job = tid; job < PPB * 312; job += TPB) {
        int lp  = job / 312;
        int rem = job - lp * 312;
        int k3  = rem >> 3;
        int cq  = rem & 7;
        const float* r0 = &sm[S_SDH + lp * 1440 + k3 * 36 + cq * 4];        // hh=lp
        const float* r1 = &sm[S_SDH + (lp + 1) * 1440 + k3 * 36 + cq * 4];  // hh=lp+1
        float4 a0 = *(const float4*)(r0);
        float4 a1 = *(const float4*)(r0 + 36);                // k3+1
        float4 b0 = *(const float4*)(r1);
        float4 b1 = *(const float4*)(r1 + 36);
        float4 s = make_float4(
            (a0.x + a1.x + b0.x + b1.x) * 0.125f,
            (a0.y + a1.y + b0.y + b1.y) * 0.125f,
            (a0.z + a1.z + b0.z + b1.z) * 0.125f,
            (a0.w + a1.w + b0.w + b1.w) * 0.125f);
        *(float4*)&sm[S_POOL + lp * 1404 + k3 * 36 + cq * 4] = s;
    }
    __syncthreads();   // all SDH reads done; X may now overwrite SDH region

    // -------- Phase C: matvec x'[lp][k3][j] = s_k3 * (pooled @ M^T) --------
    for (int job = tid; job < PPB * 312; job += TPB) {
        int lp  = job / 312;
        int rem = job - lp * 312;
        int k3  = rem >> 3;
        int jq  = rem & 7;
        float a0 = 0.f, a1 = 0.f, a2 = 0.f, a3 = 0.f;
#pragma unroll
        for (int l = 0; l < 32; l++) {
            float p4 = sm[S_POOL + lp * 1404 + k3 * 36 + l];
            float4 m4 = *(const float4*)&sm[S_MT + l * 32 + jq * 4];
            a0 += p4 * m4.x; a1 += p4 * m4.y; a2 += p4 * m4.z; a3 += p4 * m4.w;
        }
        float sgn = (k3 & 2) ? -1.0f : 1.0f;                  // s_k: +,+,-,-
        float* xd = &sm[S_X + lp * 1248 + k3 * 32 + jq * 4];
        xd[0] = sgn * a0; xd[1] = sgn * a1; xd[2] = sgn * a2; xd[3] = sgn * a3;
    }
    __syncthreads();

    // -------- Phase D: per-warp seeds (PT smem + g_tab rows) --------
    const int pair = pairb + wid;
    const int k1 = k1b, k2 = k2b + wid;
    const float* t1r = g_tab + k1 * 1024;
    const float* t2r = g_tab + k2 * 1024;
    const float* cr  = g_tab + 1024;                          // k=1 row: cos(a)

    ull w0[16], w1[16], p2[16], m2[16];
#pragma unroll
    for (int jp = 0; jp < 16; jp++) {
        int t0 = (2 * jp) * 32 + lane, t1 = t0 + 32;
        float pa = sm[S_PT + (2 * jp) * 33 + lane];
        float pb = sm[S_PT + (2 * jp + 1) * 33 + lane];
        float a0 = pa * t1r[t0] * t2r[t0];                    // A[i, 2jp]
        float a1 = pb * t1r[t1] * t2r[t1];                    // A[i, 2jp+1]
        float c0 = cr[t0], c1 = cr[t1];
        w0[jp] = f2_pack2(a0, a1);                            // w_0 = A
        w1[jp] = f2_pack2(a0 * c0, a1 * c1);                  // w_1 = A*c
        p2[jp] = f2_pack2(2.0f * c0, 2.0f * c1);              // +2c
        m2[jp] = f2_pack2(-2.0f * c0, -2.0f * c1);            // -2c
    }

    // -------- Phase E: march k3; LDS hoisted ahead of recurrence --------
    const ulonglong2* xq = (const ulonglong2*)(sm + S_X + wid * 1248);
    float* outp = out + pair * (NP * 32) + lane;
    ulonglong2 xb[8];

#define XLOAD(K3) do { _Pragma("unroll")                                  \
    for (int q = 0; q < 8; q++) xb[q] = xq[(K3) * 8 + q]; } while (0)

#define DOT_TAIL(W, K3) do {                                              \
    ull a0 = 0, a1 = 0, a2 = 0, a3 = 0;                                   \
    _Pragma("unroll")                                                     \
    for (int q = 0; q < 8; q += 2) {                                      \
        a0 = f2_fma(W[2*q + 0], xb[q].x,     a0);                         \
        a1 = f2_fma(W[2*q + 1], xb[q].y,     a1);                         \
        a2 = f2_fma(W[2*q + 2], xb[q + 1].x, a2);                         \
        a3 = f2_fma(W[2*q + 3], xb[q + 1].y, a3);                         \
    }                                                                     \
    float2 fr = f2_unpack(f2_add(f2_add(a0, a1), f2_add(a2, a3)));        \
    outp[(K3) * 32] = fr.x + fr.y;                                        \
} while (0)

    XLOAD(0); DOT_TAIL(w0, 0);
    XLOAD(1); DOT_TAIL(w1, 1);

#pragma unroll 1
    for (int k3 = 2; k3 < 38; k3 += 2) {
        XLOAD(k3);
#pragma unroll
        for (int jp = 0; jp < 16; jp++)
            w0[jp] = f2_fma(m2[jp], w1[jp], w0[jp]);          // even: -2c*w1 + w0
        DOT_TAIL(w0, k3);
        XLOAD(k3 + 1);
#pragma unroll
        for (int jp = 0; jp < 16; jp++)
            w1[jp] = f2_fma(p2[jp], w0[jp], w1[jp]);          // odd: +2c*w0 + w1
        DOT_TAIL(w1, k3 + 1);
    }
    XLOAD(38);
#pragma unroll
    for (int jp = 0; jp < 16; jp++)
        w0[jp] = f2_fma(m2[jp], w1[jp], w0[jp]);
    DOT_TAIL(w0, 38);
#undef XLOAD
#undef DOT_TAIL
}

// ---------------------------------------------------------------------------
extern "C" void kernel_launch(void* const* d_in, const int* in_sizes, int n_in,
                              void* d_out, int out_size) {
    const float* vol = (const float*)d_in[0];
    const float* M   = (const float*)d_in[1];
    const float* P   = (const float*)d_in[2];
    float* out = (float*)d_out;

    k_pre <<<4, 256>>>();
    k_main<<<NPAIR / PPB, TPB>>>(vol, M, P, out);   // 507 blocks
}

// round 14
// speedup vs baseline: 1.0620x; 1.0620x over previous
#include <cuda_runtime.h>

// Problem: volume [40,40,40,32] f32, M [32,32], P [32,32] -> Nk [59319,32]
//   b = (k1*39 + k2)*39 + k3
//   Nk[b,i] = sum_j x[b,j] * P[i,j] * cos(k1*a_ij) * cos(k2*a_ij) * cos(k3*a_ij)
//   a_ij = 2pi/(i*32+j+2),  x = (2x2x2 mean pool) @ M^T
//
// R14 = R10 (register-resident Chebyshev march, WPB=11, single wave) with
// pooling restructured: dd-summed volume rows staged ONCE per block into
// dedup'd slots (<=13 rows incl. k1-straddle), pooled windows then built
// from smem sliding sums. 3.3x fewer LDGs in phase A/B.
#define NP    39
#define NPAIR (39*39)     // 1521
#define WPB   11          // pairs (warps) per block
#define TPB   (WPB*32)    // 352
#define PI2F  6.2831853071795864769f

typedef unsigned long long ull;

__device__ float g_tab[39 * 1024];   // tab[k][j*32+i] = cos(k*2pi/(i*32+j+2))

// ---- f32x2 packed math (sm_103a) ------------------------------------------
__device__ __forceinline__ ull f2_fma(ull a, ull b, ull c) {
    ull d; asm("fma.rn.f32x2 %0, %1, %2, %3;" : "=l"(d) : "l"(a), "l"(b), "l"(c)); return d;
}
__device__ __forceinline__ ull f2_add(ull a, ull b) {
    ull d; asm("add.rn.f32x2 %0, %1, %2;" : "=l"(d) : "l"(a), "l"(b)); return d;
}
__device__ __forceinline__ ull f2_pack2(float lo, float hi) {
    ull d; asm("mov.b64 %0, {%1, %2};" : "=l"(d) : "f"(lo), "f"(hi)); return d;
}
__device__ __forceinline__ float2 f2_unpack(ull v) {
    float2 r; asm("mov.b64 {%0, %1}, %2;" : "=f"(r.x), "=f"(r.y) : "l"(v)); return r;
}

// ---------------------------------------------------------------------------
// Kernel 0: cos table via Chebyshev recurrence. grid 4 x 256.
// ---------------------------------------------------------------------------
__global__ void k_pre() {
    int t = blockIdx.x * 256 + threadIdx.x;   // t = j*32 + i
    int i = t & 31, j = t >> 5;
    float a  = PI2F / (float)(i * 32 + j + 2);
    float c1 = cosf(a);
    float twoc = 2.0f * c1;
    float cm2 = 1.0f, cm1 = c1;
    g_tab[t]        = 1.0f;
    g_tab[1024 + t] = c1;
#pragma unroll
    for (int k = 2; k < 39; k++) {
        float ck = twoc * cm1 - cm2;
        g_tab[k * 1024 + t] = ck;
        cm2 = cm1; cm1 = ck;
    }
}

// ---------------------------------------------------------------------------
// Main kernel: grid 139 x 352 threads, 145.1 KB dynamic smem, 1 block/SM.
// ---------------------------------------------------------------------------
// smem float offsets:
#define S_PT    0        // 1056   P^T padded [j*33 + i]
#define S_MT    1056     // 1024   MT[l*32 + j] = M[j][l]
#define S_TAB   2080     // 32     int tables: rowinfo[13], s0tab[11], S
#define S_SDH   2112     // 13*1440 = 18720  dd-summed rows [slot][k3r*36+ch]
#define S_X     2112     // 11*1248 = 13728  x'[lp][k3*32+j]  (overlaps SDH)
#define S_POOL  20832    // 11*1404 = 15444  pooled[lp][k3*36+ch]
#define SM_FLOATS 36276

__global__ void __launch_bounds__(TPB) k_main(
    const float* __restrict__ vol, const float* __restrict__ Mw,
    const float* __restrict__ P, float* __restrict__ out)
{
    extern __shared__ float sm[];
    int* rowinfo = (int*)(sm + S_TAB);        // [13]: k1r*64 + k2r
    int* s0tab   = rowinfo + 13;              // [11]: first slot per pair
    int* Sp      = rowinfo + 24;              // slot count

    const int tid  = threadIdx.x;
    const int lane = tid & 31;
    const int wid  = tid >> 5;
    const int p0   = blockIdx.x * WPB;
    const int pair = p0 + wid;
    const bool valid = (pair < NPAIR);

    // -------- Phase 0: thread 0 builds the dedup'd row-slot tables --------
    if (tid == 0) {
        int S = 0, pk1 = -1, pk2 = -1, ps0 = -1;
        for (int lp = 0; lp < WPB; lp++) {
            int pr = p0 + lp; if (pr > NPAIR - 1) pr = NPAIR - 1;
            int k1 = pr / 39, k2 = pr - k1 * 39;
            int s0;
            if (lp > 0 && k1 == pk1 && k2 == pk2) {
                s0 = ps0;                                   // exact repeat (clamp)
            } else if (lp > 0 && k1 == pk1 && k2 == pk2 + 1) {
                s0 = ps0 + 1;                               // share row k2
                if (s0 + 1 >= S) { rowinfo[S] = k1 * 64 + (k2 + 1); S++; }
            } else {
                s0 = S; rowinfo[S] = k1 * 64 + k2; S++;
                rowinfo[S] = k1 * 64 + (k2 + 1); S++;
            }
            s0tab[lp] = s0;
            pk1 = k1; pk2 = k2; ps0 = s0;
        }
        *Sp = S;
    }
    // -------- Phase A: stage P^T (padded) and MT --------
    for (int g = tid; g < 1024; g += TPB) {
        sm[S_PT + (g & 31) * 33 + (g >> 5)] = P[g];           // PT[j][i] = P[i][j]
        sm[S_MT + g] = Mw[(g & 31) * 32 + (g >> 5)];          // MT[l][j] = M[j][l]
    }
    __syncthreads();

    // -------- Phase A2: dd-summed row staging (2 LDGs per job) --------
    const int S = *Sp;
    for (int idx = tid; idx < 13 * 320; idx += TPB) {
        int s = idx / 320;
        if (s >= S) continue;
        int r   = idx - s * 320;
        int k3r = r >> 3;
        int cq  = r & 7;
        int info = rowinfo[s];
        int k1r = info >> 6, k2r = info & 63;
        const float* base = vol + ((k1r * 40 + k2r) * 40 + k3r) * 32 + cq * 4;
        float4 v0 = *(const float4*)(base);
        float4 v1 = *(const float4*)(base + 51200);           // k1r + 1
        *(float4*)&sm[S_SDH + s * 1440 + k3r * 36 + cq * 4] =
            make_float4(v0.x + v1.x, v0.y + v1.y, v0.z + v1.z, v0.w + v1.w);
    }
    __syncthreads();

    // -------- Phase B: sliding-window combine -> pooled (x 0.125) --------
    for (int job = tid; job < WPB * 312; job += TPB) {
        int lp  = job / 312;
        int rem = job - lp * 312;
        int k3  = rem >> 3;
        int cq  = rem & 7;
        int s0  = s0tab[lp];
        const float* r0 = &sm[S_SDH + s0 * 1440 + k3 * 36 + cq * 4];
        const float* r1 = r0 + 1440;                          // slot s0+1
        float4 a0 = *(const float4*)(r0);
        float4 a1 = *(const float4*)(r0 + 36);                // k3+1
        float4 b0 = *(const float4*)(r1);
        float4 b1 = *(const float4*)(r1 + 36);
        *(float4*)&sm[S_POOL + lp * 1404 + k3 * 36 + cq * 4] = make_float4(
            (a0.x + a1.x + b0.x + b1.x) * 0.125f,
            (a0.y + a1.y + b0.y + b1.y) * 0.125f,
            (a0.z + a1.z + b0.z + b1.z) * 0.125f,
            (a0.w + a1.w + b0.w + b1.w) * 0.125f);
    }
    __syncthreads();   // SDH consumed; X may overwrite it

    // -------- Phase C: matvec x'[lp][k3][j] = s_k3 * (pooled @ M^T) --------
    for (int job = tid; job < WPB * 312; job += TPB) {
        int lp  = job / 312;
        int rem = job - lp * 312;
        int k3  = rem >> 3;
        int jq  = rem & 7;
        float a0 = 0.f, a1 = 0.f, a2 = 0.f, a3 = 0.f;
#pragma unroll
        for (int l = 0; l < 32; l++) {
            float p4 = sm[S_POOL + lp * 1404 + k3 * 36 + l];
            float4 m4 = *(const float4*)&sm[S_MT + l * 32 + jq * 4];
            a0 += p4 * m4.x; a1 += p4 * m4.y; a2 += p4 * m4.z; a3 += p4 * m4.w;
        }
        float sgn = (k3 & 2) ? -1.0f : 1.0f;                  // s_k: +,+,-,-
        float* xd = &sm[S_X + lp * 1248 + k3 * 32 + jq * 4];
        xd[0] = sgn * a0; xd[1] = sgn * a1; xd[2] = sgn * a2; xd[3] = sgn * a3;
    }
    __syncthreads();

    if (!valid) return;                                       // no syncs after this

    // -------- Phase D: per-warp seeds (PT smem + g_tab rows) --------
    const int k1 = pair / 39, k2 = pair - (pair / 39) * 39;
    const float* t1r = g_tab + k1 * 1024;
    const float* t2r = g_tab + k2 * 1024;
    const float* cr  = g_tab + 1024;                          // k=1 row: cos(a)

    ull w0[16], w1[16], p2[16], m2[16];
#pragma unroll
    for (int jp = 0; jp < 16; jp++) {
        int t0 = (2 * jp) * 32 + lane, t1 = t0 + 32;
        float pa = sm[S_PT + (2 * jp) * 33 + lane];
        float pb = sm[S_PT + (2 * jp + 1) * 33 + lane];
        float a0 = pa * t1r[t0] * t2r[t0];                    // A[i, 2jp]
        float a1 = pb * t1r[t1] * t2r[t1];                    // A[i, 2jp+1]
        float c0 = cr[t0], c1 = cr[t1];
        w0[jp] = f2_pack2(a0, a1);                            // w_0 = A
        w1[jp] = f2_pack2(a0 * c0, a1 * c1);                  // w_1 = A*c
        p2[jp] = f2_pack2(2.0f * c0, 2.0f * c1);              // +2c
        m2[jp] = f2_pack2(-2.0f * c0, -2.0f * c1);            // -2c
    }

    // -------- Phase E: march k3; x-row LDS hoisted ahead of recurrence ----
    const ulonglong2* xq = (const ulonglong2*)(sm + S_X + wid * 1248);
    float* outp = out + pair * (NP * 32) + lane;
    ulonglong2 xb[8];

#define XLOAD(K3) do { _Pragma("unroll")                                  \
    for (int q = 0; q < 8; q++) xb[q] = xq[(K3) * 8 + q]; } while (0)

#define DOT_TAIL(W, K3) do {                                              \
    ull a0 = 0, a1 = 0, a2 = 0, a3 = 0;                                   \
    _Pragma("unroll")                                                     \
    for (int q = 0; q < 8; q += 2) {                                      \
        a0 = f2_fma(W[2*q + 0], xb[q].x,     a0);                         \
        a1 = f2_fma(W[2*q + 1], xb[q].y,     a1);                         \
        a2 = f2_fma(W[2*q + 2], xb[q + 1].x, a2);                         \
        a3 = f2_fma(W[2*q + 3], xb[q + 1].y, a3);                         \
    }                                                                     \
    float2 fr = f2_unpack(f2_add(f2_add(a0, a1), f2_add(a2, a3)));        \
    outp[(K3) * 32] = fr.x + fr.y;                                        \
} while (0)

    XLOAD(0); DOT_TAIL(w0, 0);
    XLOAD(1); DOT_TAIL(w1, 1);

#pragma unroll 1
    for (int k3 = 2; k3 < 38; k3 += 2) {
        XLOAD(k3);
#pragma unroll
        for (int jp = 0; jp < 16; jp++)
            w0[jp] = f2_fma(m2[jp], w1[jp], w0[jp]);          // even: -2c*w1 + w0
        DOT_TAIL(w0, k3);
        XLOAD(k3 + 1);
#pragma unroll
        for (int jp = 0; jp < 16; jp++)
            w1[jp] = f2_fma(p2[jp], w0[jp], w1[jp]);          // odd: +2c*w0 + w1
        DOT_TAIL(w1, k3 + 1);
    }
    XLOAD(38);
#pragma unroll
    for (int jp = 0; jp < 16; jp++)
        w0[jp] = f2_fma(m2[jp], w1[jp], w0[jp]);
    DOT_TAIL(w0, 38);
#undef XLOAD
#undef DOT_TAIL
}

// ---------------------------------------------------------------------------
extern "C" void kernel_launch(void* const* d_in, const int* in_sizes, int n_in,
                              void* d_out, int out_size) {
    const float* vol = (const float*)d_in[0];
    const float* M   = (const float*)d_in[1];
    const float* P   = (const float*)d_in[2];
    float* out = (float*)d_out;

    static int attr_set = 0;
    if (!attr_set) {
        cudaFuncSetAttribute(k_main, cudaFuncAttributeMaxDynamicSharedMemorySize,
                             SM_FLOATS * 4);
        attr_set = 1;
    }
    const int nblk = (NPAIR + WPB - 1) / WPB;   // 139
    k_pre <<<4, 256>>>();
    k_main<<<nblk, TPB, SM_FLOATS * 4>>>(vol, M, P, out);
}